// round 10
// baseline (speedup 1.0000x reference)
#include <cuda_runtime.h>
#include <cuda_bf16.h>

#define N_NODES 50000
#define N_EDGES 800000
#define NUM_GRAPHS 256
#define D 64
#define EPS 1e-5f

#define SCAN_T 1024
#define SCAN_C 49   // 1024*49 = 50176 >= 50000

// ---------------- scratch (device globals; no allocation) ----------------
// State contract: g_deg and g_pooled are ZERO at entry to every kernel_launch
// invocation (zero-initialized at load; re-zeroed by k_place / k_mlp each run).
__device__ float g_xw[N_NODES * D];      // dinv[n] * (A @ W)[n]
__device__ float g_agg[N_NODES * D];     // layer-0 output
__device__ float g_deg[N_NODES];         // in-degree (no self-loop), zeroed each run
__device__ float g_dinv[N_NODES];
__device__ int   g_esrc[N_EDGES];        // source ids, grouped by target (CSR)
__device__ int   g_startv[N_NODES];      // CSR row start
__device__ int   g_pos[N_NODES];         // placement cursor -> row end
__device__ float g_pooled[NUM_GRAPHS * D]; // zeroed each run (by k_mlp)

// ---------------- degree count (g_deg starts at 0) ----------------
__global__ void k_deg_count(const int* __restrict__ col) {
    int e = blockIdx.x * blockDim.x + threadIdx.x;
    if (e < N_EDGES) atomicAdd(&g_deg[col[e]], 1.0f);
}

// ---------------- single-block scan: dinv + CSR row starts ----------------
__global__ void k_scan() {
    __shared__ int sh[SCAN_T];
    int t = threadIdx.x;
    int n0 = t * SCAN_C;
    int deg[SCAN_C];
    int sum = 0;
    #pragma unroll
    for (int i = 0; i < SCAN_C; i++) {
        int n = n0 + i;
        int d = 0;
        if (n < N_NODES) {
            float df = g_deg[n];
            g_dinv[n] = rsqrtf(df + 1.0f);   // +1 self-loop
            d = (int)df;
        }
        deg[i] = d;
        sum += d;
    }
    sh[t] = sum;
    __syncthreads();
    // Hillis-Steele inclusive scan over 1024 thread sums
    #pragma unroll
    for (int off = 1; off < SCAN_T; off <<= 1) {
        int add = (t >= off) ? sh[t - off] : 0;
        __syncthreads();
        sh[t] += add;
        __syncthreads();
    }
    int running = sh[t] - sum;  // exclusive prefix
    #pragma unroll
    for (int i = 0; i < SCAN_C; i++) {
        int n = n0 + i;
        if (n < N_NODES) {
            g_startv[n] = running;
            g_pos[n] = running;
            running += deg[i];
        }
    }
}

// ---------------- place edges + restore g_deg to zero for next replay ----------------
__global__ void k_place(const int* __restrict__ row, const int* __restrict__ col) {
    int e = blockIdx.x * blockDim.x + threadIdx.x;
    if (e < N_NODES) g_deg[e] = 0.0f;   // state restore (scan already consumed g_deg)
    if (e >= N_EDGES) return;
    int c = col[e];
    int slot = atomicAdd(&g_pos[c], 1);
    g_esrc[slot] = row[e];
}

// ---------------- GEMM: C[n,:] = dinv[n] * (A[n,:] @ W)  (4x4 register tile) ----------------
__global__ void k_gemm64(const float* __restrict__ A,
                         const float* __restrict__ W,
                         float* __restrict__ C) {
    __shared__ float  As[64][65];
    __shared__ float4 Ws4[64][16];
    int tid = threadIdx.x;
    int row0 = blockIdx.x * 64;

    #pragma unroll
    for (int i = tid; i < 1024; i += 256)
        Ws4[i >> 4][i & 15] = ((const float4*)W)[i];
    #pragma unroll
    for (int i = tid; i < 4096; i += 256) {
        int r = i >> 6, c = i & 63;
        As[r][c] = (row0 + r < N_NODES) ? A[(row0 + r) * D + c] : 0.0f;
    }
    __syncthreads();

    int tx = tid & 15;
    int ty = tid >> 4;

    float4 acc0 = {0,0,0,0}, acc1 = {0,0,0,0}, acc2 = {0,0,0,0}, acc3 = {0,0,0,0};

    #pragma unroll
    for (int k = 0; k < 64; k++) {
        float4 w = Ws4[k][tx];
        float a0 = As[ty * 4 + 0][k];
        float a1 = As[ty * 4 + 1][k];
        float a2 = As[ty * 4 + 2][k];
        float a3 = As[ty * 4 + 3][k];
        acc0.x = fmaf(a0, w.x, acc0.x); acc0.y = fmaf(a0, w.y, acc0.y);
        acc0.z = fmaf(a0, w.z, acc0.z); acc0.w = fmaf(a0, w.w, acc0.w);
        acc1.x = fmaf(a1, w.x, acc1.x); acc1.y = fmaf(a1, w.y, acc1.y);
        acc1.z = fmaf(a1, w.z, acc1.z); acc1.w = fmaf(a1, w.w, acc1.w);
        acc2.x = fmaf(a2, w.x, acc2.x); acc2.y = fmaf(a2, w.y, acc2.y);
        acc2.z = fmaf(a2, w.z, acc2.z); acc2.w = fmaf(a2, w.w, acc2.w);
        acc3.x = fmaf(a3, w.x, acc3.x); acc3.y = fmaf(a3, w.y, acc3.y);
        acc3.z = fmaf(a3, w.z, acc3.z); acc3.w = fmaf(a3, w.w, acc3.w);
    }

    #pragma unroll
    for (int i = 0; i < 4; i++) {
        int r = row0 + ty * 4 + i;
        if (r < N_NODES) {
            float d = g_dinv[r];
            float4 v = (i == 0) ? acc0 : (i == 1) ? acc1 : (i == 2) ? acc2 : acc3;
            v.x *= d; v.y *= d; v.z *= d; v.w *= d;
            *((float4*)(C + r * D) + tx) = v;
        }
    }
}

// ---------------- gather-aggregate + self-loop + bias + BN + ReLU ----------------
// do_pool=0: write node row to g_agg.  do_pool=1: atomically accumulate into
// g_pooled[batch[w]] (fused global mean pool numerator).
__global__ void k_agg(const float* __restrict__ b,
                      const float* __restrict__ bg,
                      const float* __restrict__ bb,
                      const float* __restrict__ bm,
                      const float* __restrict__ bv,
                      const int* __restrict__ batch,
                      int do_pool) {
    int w = (blockIdx.x * blockDim.x + threadIdx.x) >> 5;
    int lane = threadIdx.x & 31;
    if (w >= N_NODES) return;
    int s0 = g_startv[w];
    int s1 = g_pos[w];
    int cb = 2 * lane;

    float2 acc = *(const float2*)(g_xw + w * D + cb);  // self-loop (dinv folded)
    for (int j = s0; j < s1; j++) {
        int r = __ldg(&g_esrc[j]);
        float2 v = *(const float2*)(g_xw + r * D + cb);
        acc.x += v.x;
        acc.y += v.y;
    }
    float dc = g_dinv[w];
    float2 bj  = *(const float2*)(b  + cb);
    float2 mj  = *(const float2*)(bm + cb);
    float2 vj  = *(const float2*)(bv + cb);
    float2 gj  = *(const float2*)(bg + cb);
    float2 bbj = *(const float2*)(bb + cb);
    float2 o;
    o.x = fmaxf((dc * acc.x + bj.x - mj.x) * rsqrtf(vj.x + EPS) * gj.x + bbj.x, 0.f);
    o.y = fmaxf((dc * acc.y + bj.y - mj.y) * rsqrtf(vj.y + EPS) * gj.y + bbj.y, 0.f);
    if (do_pool) {
        int g = __ldg(&batch[w]);
        atomicAdd(&g_pooled[g * D + cb],     o.x);
        atomicAdd(&g_pooled[g * D + cb + 1], o.y);
    } else {
        *(float2*)(g_agg + w * D + cb) = o;
    }
}

// ---------------- MLP head (+ cnt via binary search, + g_pooled restore) ----------------
__global__ void k_mlp(const int* __restrict__ batch,
                      const float* __restrict__ hW1, const float* __restrict__ hb1,
                      const float* __restrict__ hg1, const float* __restrict__ hbb1,
                      const float* __restrict__ hm1, const float* __restrict__ hv1,
                      const float* __restrict__ hW2, const float* __restrict__ hb2,
                      const float* __restrict__ hg2, const float* __restrict__ hbb2,
                      const float* __restrict__ hm2, const float* __restrict__ hv2,
                      const float* __restrict__ hW3, const float* __restrict__ hb3,
                      const float* __restrict__ hW4, const float* __restrict__ hb4,
                      float* __restrict__ out) {
    __shared__ float p[64];
    __shared__ float z1[256];
    __shared__ float z2[128];
    __shared__ float z3[64];
    int g = blockIdx.x;
    int tid = threadIdx.x;
    if (tid < 64) {
        // cnt[g] = (first idx with batch >= g+1) - (first idx with batch >= g)
        // batch is sorted; warp-uniform binary searches (all lanes same path).
        int lo = 0, hi = N_NODES;
        while (lo < hi) { int m = (lo + hi) >> 1; if (__ldg(&batch[m]) < g) lo = m + 1; else hi = m; }
        int a = lo;
        lo = 0; hi = N_NODES;
        while (lo < hi) { int m = (lo + hi) >> 1; if (__ldg(&batch[m]) < g + 1) lo = m + 1; else hi = m; }
        float c = fmaxf((float)(lo - a), 1.0f);
        p[tid] = g_pooled[g * D + tid] / c;
        g_pooled[g * D + tid] = 0.0f;   // state restore for next replay
    }
    __syncthreads();
    {
        float acc = hb1[tid];
        #pragma unroll
        for (int k = 0; k < 64; k++) acc = fmaf(p[k], hW1[k * 256 + tid], acc);
        acc = (acc - hm1[tid]) * rsqrtf(hv1[tid] + EPS) * hg1[tid] + hbb1[tid];
        z1[tid] = fmaxf(acc, 0.0f);
    }
    __syncthreads();
    if (tid < 128) {
        float acc = hb2[tid];
        #pragma unroll 8
        for (int k = 0; k < 256; k++) acc = fmaf(z1[k], hW2[k * 128 + tid], acc);
        acc = (acc - hm2[tid]) * rsqrtf(hv2[tid] + EPS) * hg2[tid] + hbb2[tid];
        z2[tid] = fmaxf(acc, 0.0f);
    }
    __syncthreads();
    if (tid < 64) {
        float acc = hb3[tid];
        #pragma unroll 8
        for (int k = 0; k < 128; k++) acc = fmaf(z2[k], hW3[k * 64 + tid], acc);
        z3[tid] = fmaxf(acc, 0.0f);
    }
    __syncthreads();
    if (tid == 0) {
        float acc = hb4[0];
        #pragma unroll
        for (int k = 0; k < 64; k++) acc = fmaf(z3[k], hW4[k], acc);
        out[g] = acc;
    }
}

// ---------------- launch ----------------
extern "C" void kernel_launch(void* const* d_in, const int* in_sizes, int n_in,
                              void* d_out, int out_size) {
    const float* x      = (const float*)d_in[0];
    const int*   ei     = (const int*)d_in[1];
    const int*   batch  = (const int*)d_in[2];
    const float* gcn_W0 = (const float*)d_in[3];
    const float* gcn_b0 = (const float*)d_in[4];
    const float* bn_g0  = (const float*)d_in[5];
    const float* bn_b0  = (const float*)d_in[6];
    const float* bn_m0  = (const float*)d_in[7];
    const float* bn_v0  = (const float*)d_in[8];
    const float* gcn_W1 = (const float*)d_in[9];
    const float* gcn_b1 = (const float*)d_in[10];
    const float* bn_g1  = (const float*)d_in[11];
    const float* bn_b1  = (const float*)d_in[12];
    const float* bn_m1  = (const float*)d_in[13];
    const float* bn_v1  = (const float*)d_in[14];
    const float* hW1 = (const float*)d_in[15];
    const float* hb1 = (const float*)d_in[16];
    const float* hg1 = (const float*)d_in[17];
    const float* hbb1= (const float*)d_in[18];
    const float* hm1 = (const float*)d_in[19];
    const float* hv1 = (const float*)d_in[20];
    const float* hW2 = (const float*)d_in[21];
    const float* hb2 = (const float*)d_in[22];
    const float* hg2 = (const float*)d_in[23];
    const float* hbb2= (const float*)d_in[24];
    const float* hm2 = (const float*)d_in[25];
    const float* hv2 = (const float*)d_in[26];
    const float* hW3 = (const float*)d_in[27];
    const float* hb3 = (const float*)d_in[28];
    const float* hW4 = (const float*)d_in[29];
    const float* hb4 = (const float*)d_in[30];
    float* out = (float*)d_out;

    const int* erow = ei;
    const int* ecol = ei + N_EDGES;

    float *p_xw = nullptr, *p_agg = nullptr;
    cudaGetSymbolAddress((void**)&p_xw, g_xw);
    cudaGetSymbolAddress((void**)&p_agg, g_agg);

    const int T = 256;
    int gE    = (N_EDGES + T - 1) / T;
    int gRows = (N_NODES + 63) / 64;
    int gAgg  = (int)(((long long)N_NODES * 32 + T - 1) / T);

    // CSR build (4 kernels)
    k_deg_count<<<gE, T>>>(ecol);
    k_scan<<<1, SCAN_T>>>();
    k_place<<<gE, T>>>(erow, ecol);

    // GCN layer 0
    k_gemm64<<<gRows, T>>>(x, gcn_W0, p_xw);
    k_agg<<<gAgg, T>>>(gcn_b0, bn_g0, bn_b0, bn_m0, bn_v0, batch, 0);

    // GCN layer 1 (+ fused mean-pool numerator)
    k_gemm64<<<gRows, T>>>(p_agg, gcn_W1, p_xw);
    k_agg<<<gAgg, T>>>(gcn_b1, bn_g1, bn_b1, bn_m1, bn_v1, batch, 1);

    // MLP head (+ cnt binary search + pooled restore)
    k_mlp<<<NUM_GRAPHS, 256>>>(batch,
                               hW1, hb1, hg1, hbb1, hm1, hv1,
                               hW2, hb2, hg2, hbb2, hm2, hv2,
                               hW3, hb3, hW4, hb4, out);
}

// round 11
// speedup vs baseline: 1.6551x; 1.6551x over previous
#include <cuda_runtime.h>
#include <cuda_bf16.h>

#define N_NODES 50000
#define N_EDGES 800000
#define NUM_GRAPHS 256
#define D 64
#define EPS 1e-5f

#define SCHUNK 196
#define SBLOCKS 256   // 256*196 = 50176 >= 50000

// ---------------- scratch (device globals; no allocation) ----------------
// State contract: g_deg and g_pooled are ZERO at entry to every kernel_launch
// invocation (zero-initialized at load; re-zeroed by k_place / k_mlp each run).
__device__ float g_xw[N_NODES * D];      // dinv[n] * (A @ W)[n]
__device__ float g_agg[N_NODES * D];     // layer-0 output
__device__ float g_deg[N_NODES];         // in-degree (no self-loop); zeroed each run
__device__ float g_dinv[N_NODES];
__device__ int   g_esrc[N_EDGES];        // source ids, grouped by target (CSR)
__device__ int   g_startv[N_NODES];      // CSR row start
__device__ int   g_pos[N_NODES];         // placement cursor -> row end
__device__ int   g_part[SBLOCKS];
__device__ float g_pooled[NUM_GRAPHS * D]; // zeroed each run (by k_mlp)

// ---------------- degree count (g_deg starts at 0) ----------------
__global__ void k_deg_count(const int* __restrict__ col) {
    int e = blockIdx.x * blockDim.x + threadIdx.x;
    if (e < N_EDGES) atomicAdd(&g_deg[col[e]], 1.0f);
}

// ---------------- scan phase 1: per-chunk totals (+ dinv fused) ----------------
__global__ void k_scan_partial() {
    __shared__ int sh[256];
    int b = blockIdx.x, t = threadIdx.x;
    int n = b * SCHUNK + t;
    int v = 0;
    if (t < SCHUNK && n < N_NODES) {
        float d = g_deg[n];
        g_dinv[n] = rsqrtf(d + 1.0f);   // +1 self-loop
        v = (int)d;
    }
    sh[t] = v;
    __syncthreads();
    for (int off = 128; off > 0; off >>= 1) {
        if (t < off) sh[t] += sh[t + off];
        __syncthreads();
    }
    if (t == 0) g_part[b] = sh[0];
}

// ---------------- scan phase 2: chunk scan with inline base reduction ----------------
__global__ void k_scan_chunk() {
    __shared__ int sh[256];
    __shared__ int bs[256];
    int b = blockIdx.x, t = threadIdx.x;
    bs[t] = (t < b) ? g_part[t] : 0;
    int n = b * SCHUNK + t;
    int v = 0;
    if (t < SCHUNK && n < N_NODES) v = (int)g_deg[n];
    sh[t] = v;
    __syncthreads();
    for (int off = 128; off > 0; off >>= 1) {
        if (t < off) bs[t] += bs[t + off];
        __syncthreads();
    }
    for (int off = 1; off < 256; off <<= 1) {
        int add = (t >= off) ? sh[t - off] : 0;
        __syncthreads();
        sh[t] += add;
        __syncthreads();
    }
    if (t < SCHUNK && n < N_NODES) {
        int start = bs[0] + sh[t] - v;
        g_startv[n] = start;
        g_pos[n] = start;
    }
}

// ---------------- place edges + restore g_deg to zero for next replay ----------------
__global__ void k_place(const int* __restrict__ row, const int* __restrict__ col) {
    int e = blockIdx.x * blockDim.x + threadIdx.x;
    if (e < N_NODES) g_deg[e] = 0.0f;   // state restore (scan already consumed g_deg)
    if (e >= N_EDGES) return;
    int c = col[e];
    int slot = atomicAdd(&g_pos[c], 1);
    g_esrc[slot] = row[e];
}

// ---------------- GEMM: C[n,:] = dinv[n] * (A[n,:] @ W)  (4x4 register tile) ----------------
__global__ void k_gemm64(const float* __restrict__ A,
                         const float* __restrict__ W,
                         float* __restrict__ C) {
    __shared__ float  As[64][65];
    __shared__ float4 Ws4[64][16];
    int tid = threadIdx.x;
    int row0 = blockIdx.x * 64;

    #pragma unroll
    for (int i = tid; i < 1024; i += 256)
        Ws4[i >> 4][i & 15] = ((const float4*)W)[i];
    #pragma unroll
    for (int i = tid; i < 4096; i += 256) {
        int r = i >> 6, c = i & 63;
        As[r][c] = (row0 + r < N_NODES) ? A[(row0 + r) * D + c] : 0.0f;
    }
    __syncthreads();

    int tx = tid & 15;
    int ty = tid >> 4;

    float4 acc0 = {0,0,0,0}, acc1 = {0,0,0,0}, acc2 = {0,0,0,0}, acc3 = {0,0,0,0};

    #pragma unroll
    for (int k = 0; k < 64; k++) {
        float4 w = Ws4[k][tx];
        float a0 = As[ty * 4 + 0][k];
        float a1 = As[ty * 4 + 1][k];
        float a2 = As[ty * 4 + 2][k];
        float a3 = As[ty * 4 + 3][k];
        acc0.x = fmaf(a0, w.x, acc0.x); acc0.y = fmaf(a0, w.y, acc0.y);
        acc0.z = fmaf(a0, w.z, acc0.z); acc0.w = fmaf(a0, w.w, acc0.w);
        acc1.x = fmaf(a1, w.x, acc1.x); acc1.y = fmaf(a1, w.y, acc1.y);
        acc1.z = fmaf(a1, w.z, acc1.z); acc1.w = fmaf(a1, w.w, acc1.w);
        acc2.x = fmaf(a2, w.x, acc2.x); acc2.y = fmaf(a2, w.y, acc2.y);
        acc2.z = fmaf(a2, w.z, acc2.z); acc2.w = fmaf(a2, w.w, acc2.w);
        acc3.x = fmaf(a3, w.x, acc3.x); acc3.y = fmaf(a3, w.y, acc3.y);
        acc3.z = fmaf(a3, w.z, acc3.z); acc3.w = fmaf(a3, w.w, acc3.w);
    }

    #pragma unroll
    for (int i = 0; i < 4; i++) {
        int r = row0 + ty * 4 + i;
        if (r < N_NODES) {
            float d = g_dinv[r];
            float4 v = (i == 0) ? acc0 : (i == 1) ? acc1 : (i == 2) ? acc2 : acc3;
            v.x *= d; v.y *= d; v.z *= d; v.w *= d;
            *((float4*)(C + r * D) + tx) = v;
        }
    }
}

// ---------------- gather-aggregate + self-loop + bias + BN + ReLU ----------------
// do_pool=0: write node row to g_agg.  do_pool=1: atomically accumulate into
// g_pooled[batch[w]] (fused global mean pool numerator).
__global__ void k_agg(const float* __restrict__ b,
                      const float* __restrict__ bg,
                      const float* __restrict__ bb,
                      const float* __restrict__ bm,
                      const float* __restrict__ bv,
                      const int* __restrict__ batch,
                      int do_pool) {
    int w = (blockIdx.x * blockDim.x + threadIdx.x) >> 5;
    int lane = threadIdx.x & 31;
    if (w >= N_NODES) return;
    int s0 = g_startv[w];
    int s1 = g_pos[w];
    int cb = 2 * lane;

    float2 acc = *(const float2*)(g_xw + w * D + cb);  // self-loop (dinv folded)
    for (int j = s0; j < s1; j++) {
        int r = __ldg(&g_esrc[j]);
        float2 v = *(const float2*)(g_xw + r * D + cb);
        acc.x += v.x;
        acc.y += v.y;
    }
    float dc = g_dinv[w];
    float2 bj  = *(const float2*)(b  + cb);
    float2 mj  = *(const float2*)(bm + cb);
    float2 vj  = *(const float2*)(bv + cb);
    float2 gj  = *(const float2*)(bg + cb);
    float2 bbj = *(const float2*)(bb + cb);
    float2 o;
    o.x = fmaxf((dc * acc.x + bj.x - mj.x) * rsqrtf(vj.x + EPS) * gj.x + bbj.x, 0.f);
    o.y = fmaxf((dc * acc.y + bj.y - mj.y) * rsqrtf(vj.y + EPS) * gj.y + bbj.y, 0.f);
    if (do_pool) {
        int g = __ldg(&batch[w]);
        atomicAdd(&g_pooled[g * D + cb],     o.x);
        atomicAdd(&g_pooled[g * D + cb + 1], o.y);
    } else {
        *(float2*)(g_agg + w * D + cb) = o;
    }
}

// ---------------- MLP head (+ cnt via binary search, + g_pooled restore) ----------------
__global__ void k_mlp(const int* __restrict__ batch,
                      const float* __restrict__ hW1, const float* __restrict__ hb1,
                      const float* __restrict__ hg1, const float* __restrict__ hbb1,
                      const float* __restrict__ hm1, const float* __restrict__ hv1,
                      const float* __restrict__ hW2, const float* __restrict__ hb2,
                      const float* __restrict__ hg2, const float* __restrict__ hbb2,
                      const float* __restrict__ hm2, const float* __restrict__ hv2,
                      const float* __restrict__ hW3, const float* __restrict__ hb3,
                      const float* __restrict__ hW4, const float* __restrict__ hb4,
                      float* __restrict__ out) {
    __shared__ float p[64];
    __shared__ float z1[256];
    __shared__ float z2[128];
    __shared__ float z3[64];
    int g = blockIdx.x;
    int tid = threadIdx.x;
    if (tid < 64) {
        // cnt[g] via two binary searches on sorted batch (warp-uniform path)
        int lo = 0, hi = N_NODES;
        while (lo < hi) { int m = (lo + hi) >> 1; if (__ldg(&batch[m]) < g) lo = m + 1; else hi = m; }
        int a = lo;
        lo = 0; hi = N_NODES;
        while (lo < hi) { int m = (lo + hi) >> 1; if (__ldg(&batch[m]) < g + 1) lo = m + 1; else hi = m; }
        float c = fmaxf((float)(lo - a), 1.0f);
        p[tid] = g_pooled[g * D + tid] / c;
        g_pooled[g * D + tid] = 0.0f;   // state restore for next replay
    }
    __syncthreads();
    {
        float acc = hb1[tid];
        #pragma unroll
        for (int k = 0; k < 64; k++) acc = fmaf(p[k], hW1[k * 256 + tid], acc);
        acc = (acc - hm1[tid]) * rsqrtf(hv1[tid] + EPS) * hg1[tid] + hbb1[tid];
        z1[tid] = fmaxf(acc, 0.0f);
    }
    __syncthreads();
    if (tid < 128) {
        float acc = hb2[tid];
        #pragma unroll 8
        for (int k = 0; k < 256; k++) acc = fmaf(z1[k], hW2[k * 128 + tid], acc);
        acc = (acc - hm2[tid]) * rsqrtf(hv2[tid] + EPS) * hg2[tid] + hbb2[tid];
        z2[tid] = fmaxf(acc, 0.0f);
    }
    __syncthreads();
    if (tid < 64) {
        float acc = hb3[tid];
        #pragma unroll 8
        for (int k = 0; k < 128; k++) acc = fmaf(z2[k], hW3[k * 64 + tid], acc);
        z3[tid] = fmaxf(acc, 0.0f);
    }
    __syncthreads();
    if (tid == 0) {
        float acc = hb4[0];
        #pragma unroll
        for (int k = 0; k < 64; k++) acc = fmaf(z3[k], hW4[k], acc);
        out[g] = acc;
    }
}

// ---------------- launch ----------------
extern "C" void kernel_launch(void* const* d_in, const int* in_sizes, int n_in,
                              void* d_out, int out_size) {
    const float* x      = (const float*)d_in[0];
    const int*   ei     = (const int*)d_in[1];
    const int*   batch  = (const int*)d_in[2];
    const float* gcn_W0 = (const float*)d_in[3];
    const float* gcn_b0 = (const float*)d_in[4];
    const float* bn_g0  = (const float*)d_in[5];
    const float* bn_b0  = (const float*)d_in[6];
    const float* bn_m0  = (const float*)d_in[7];
    const float* bn_v0  = (const float*)d_in[8];
    const float* gcn_W1 = (const float*)d_in[9];
    const float* gcn_b1 = (const float*)d_in[10];
    const float* bn_g1  = (const float*)d_in[11];
    const float* bn_b1  = (const float*)d_in[12];
    const float* bn_m1  = (const float*)d_in[13];
    const float* bn_v1  = (const float*)d_in[14];
    const float* hW1 = (const float*)d_in[15];
    const float* hb1 = (const float*)d_in[16];
    const float* hg1 = (const float*)d_in[17];
    const float* hbb1= (const float*)d_in[18];
    const float* hm1 = (const float*)d_in[19];
    const float* hv1 = (const float*)d_in[20];
    const float* hW2 = (const float*)d_in[21];
    const float* hb2 = (const float*)d_in[22];
    const float* hg2 = (const float*)d_in[23];
    const float* hbb2= (const float*)d_in[24];
    const float* hm2 = (const float*)d_in[25];
    const float* hv2 = (const float*)d_in[26];
    const float* hW3 = (const float*)d_in[27];
    const float* hb3 = (const float*)d_in[28];
    const float* hW4 = (const float*)d_in[29];
    const float* hb4 = (const float*)d_in[30];
    float* out = (float*)d_out;

    const int* erow = ei;
    const int* ecol = ei + N_EDGES;

    float *p_xw = nullptr, *p_agg = nullptr;
    cudaGetSymbolAddress((void**)&p_xw, g_xw);
    cudaGetSymbolAddress((void**)&p_agg, g_agg);

    const int T = 256;
    int gE    = (N_EDGES + T - 1) / T;
    int gRows = (N_NODES + 63) / 64;
    int gAgg  = (int)(((long long)N_NODES * 32 + T - 1) / T);

    // CSR build (3 kernels + parallel 2-phase scan)
    k_deg_count<<<gE, T>>>(ecol);
    k_scan_partial<<<SBLOCKS, 256>>>();
    k_scan_chunk<<<SBLOCKS, 256>>>();
    k_place<<<gE, T>>>(erow, ecol);

    // GCN layer 0
    k_gemm64<<<gRows, T>>>(x, gcn_W0, p_xw);
    k_agg<<<gAgg, T>>>(gcn_b0, bn_g0, bn_b0, bn_m0, bn_v0, batch, 0);

    // GCN layer 1 (+ fused mean-pool numerator)
    k_gemm64<<<gRows, T>>>(p_agg, gcn_W1, p_xw);
    k_agg<<<gAgg, T>>>(gcn_b1, bn_g1, bn_b1, bn_m1, bn_v1, batch, 1);

    // MLP head (+ cnt binary search + pooled restore)
    k_mlp<<<NUM_GRAPHS, 256>>>(batch,
                               hW1, hb1, hg1, hbb1, hm1, hv1,
                               hW2, hb2, hg2, hbb2, hm2, hv2,
                               hW3, hb3, hW4, hb4, out);
}